// round 15
// baseline (speedup 1.0000x reference)
#include <cuda_runtime.h>
#include <cuda_fp16.h>

#define Nn 200000
#define Ee 6400000
#define EPAD (Ee + 4 * Nn)
#define Gg 1024
#define C  32
#define INC 128
#define EPSF 1e-5f
#define SBLK 128          // partial slots for node-level BN stats
#define SBLK_G 8          // blocks for graph-level BN stats
#define SCB 256           // nodes per scan block
#define NSB ((Nn + SCB - 1) / SCB)   // 782 scan blocks

// ------------------------- scratch (device globals) -------------------------
__device__ int    g_edges[EPAD];      // CSR-sorted src per dst, 4-padded (pad = Nn)
__device__ int    g_degi[Nn];
__device__ int    g_rowptr[Nn + 1];   // 4-aligned segment starts
__device__ int    g_cursor[Nn];
__device__ int    g_bsum[NSB];
__device__ int    g_boff[NSB];
__device__ float  g_dis[Nn];
__device__ __half g_h[(Nn + 1) * C];  // h' = h*dis (fp16); row Nn stays zero
__device__ float  g_aggA[Nn * C];
__device__ float  g_aggB[Nn * C];
__device__ float  g_mlpA[Gg * C];
__device__ float  g_mlpB[Gg * C];
__device__ float  g_pool[Gg * C];
__device__ float  g_part[4 * SBLK * 64];  // per-pass {sum[32], sumsq[32]} slots
__device__ float  g_bnco[4 * 64];         // per-pass {scale[32], shift[32]}
__device__ int    g_is64;                 // 1 if index inputs are int64, 0 if int32

__device__ __forceinline__ const float* selbuf(int s) {
    if (s == 0) return g_aggA;
    if (s == 1) return g_aggB;
    if (s == 2) return g_mlpA;
    return g_mlpB;
}

// ------------------------- init: dtype detect + zeroing ----------------------
__global__ void k_init(const unsigned int* __restrict__ w) {
    if (blockIdx.x == 0 && threadIdx.x < 32) {
        unsigned int acc = 0;
        for (int i = threadIdx.x; i < 2048; i += 32)
            if (i & 1) acc |= w[i];
#pragma unroll
        for (int o = 16; o; o >>= 1) acc |= __shfl_down_sync(0xffffffffu, acc, o);
        if (threadIdx.x == 0) g_is64 = (acc == 0u) ? 1 : 0;
    }
    int idx = blockIdx.x * blockDim.x + threadIdx.x;
    int stride = gridDim.x * blockDim.x;
    for (int i = idx; i < Nn; i += stride)            g_degi[i] = 0;
    for (int i = idx; i < Gg * C; i += stride)        g_pool[i] = 0.f;
    for (int i = idx; i < 2 * SBLK * 64; i += stride) g_part[i] = 0.f;
    for (int i = idx; i < C; i += stride)             g_h[Nn * C + i] = __float2half(0.f);
}

// count in-degree (dst half only, 2 edges/thread, vector loads)
__global__ void k_count(const void* __restrict__ eiv) {
    int p = blockIdx.x * blockDim.x + threadIdx.x;   // pair index
    int e = p * 2;
    if (e >= Ee) return;
    int d0, d1;
    if (g_is64) {
        longlong2 v = ((const longlong2*)((const long long*)eiv + Ee))[p];
        d0 = (int)v.x; d1 = (int)v.y;
    } else {
        int2 v = ((const int2*)((const int*)eiv + Ee))[p];
        d0 = v.x; d1 = v.y;
    }
    d0 = min(max(d0, 0), Nn - 1);
    d1 = min(max(d1, 0), Nn - 1);
    if (d0 == d1) {
        atomicAdd(&g_degi[d0], 2);
    } else {
        atomicAdd(&g_degi[d0], 1);
        atomicAdd(&g_degi[d1], 1);
    }
}

// ------------------------- multi-block exclusive scan over PADDED degrees ----
__global__ void k_scan1() {
    __shared__ int sh[SCB / 32];
    int t = threadIdx.x;
    int i = blockIdx.x * SCB + t;
    int v = (i < Nn) ? ((g_degi[i] + 3) & ~3) : 0;
#pragma unroll
    for (int o = 16; o; o >>= 1) v += __shfl_down_sync(0xffffffffu, v, o);
    if ((t & 31) == 0) sh[t >> 5] = v;
    __syncthreads();
    if (t < SCB / 32) {
        int s = sh[t];
#pragma unroll
        for (int o = SCB / 64; o; o >>= 1) s += __shfl_down_sync(0xffffffffu, s, o);
        if (t == 0) g_bsum[blockIdx.x] = s;
    }
}

__global__ void k_scan2() {
    __shared__ int bs[1024];
    int t = threadIdx.x;
    int v = (t < NSB) ? g_bsum[t] : 0;
    bs[t] = v;
    __syncthreads();
    for (int o = 1; o < 1024; o <<= 1) {
        int u = (t >= o) ? bs[t - o] : 0;
        __syncthreads();
        bs[t] += u;
        __syncthreads();
    }
    if (t < NSB) g_boff[t] = bs[t] - v;          // exclusive
    if (t == NSB - 1) g_rowptr[Nn] = bs[t];      // total padded count
}

// scan3: rowptr/cursor/dis AND pad-slot fill (sort won't touch pad slots)
__global__ void k_scan3() {
    __shared__ int sh[SCB];
    int t = threadIdx.x;
    int i = blockIdx.x * SCB + t;
    int deg = (i < Nn) ? g_degi[i] : 0;
    int pdeg = (deg + 3) & ~3;
    sh[t] = pdeg;
    __syncthreads();
    int incl = pdeg;
    for (int o = 1; o < SCB; o <<= 1) {
        int u = (t >= o) ? sh[t - o] : 0;
        __syncthreads();
        incl += u;
        sh[t] = incl;
        __syncthreads();
    }
    if (i < Nn) {
        int off = g_boff[blockIdx.x] + incl - pdeg;
        g_rowptr[i] = off;
        g_cursor[i] = off;
        g_dis[i] = rsqrtf((float)deg + 1.0f);
        for (int j = off + deg; j < off + pdeg; j++) g_edges[j] = Nn;  // pads
    }
}

// ------------- counting-sort edges into padded CSR (2 edges/thread) ----------
__global__ void k_sort(const void* __restrict__ eiv) {
    int p = blockIdx.x * blockDim.x + threadIdx.x;
    int e = p * 2;
    if (e >= Ee) return;
    int s0, s1, d0, d1;
    if (g_is64) {
        const long long* ei = (const long long*)eiv;
        longlong2 sv = ((const longlong2*)ei)[p];
        longlong2 dv = ((const longlong2*)(ei + Ee))[p];
        s0 = (int)sv.x; s1 = (int)sv.y;
        d0 = (int)dv.x; d1 = (int)dv.y;
    } else {
        const int* ei = (const int*)eiv;
        int2 sv = ((const int2*)ei)[p];
        int2 dv = ((const int2*)(ei + Ee))[p];
        s0 = sv.x; s1 = sv.y;
        d0 = dv.x; d1 = dv.y;
    }
    s0 = min(max(s0, 0), Nn - 1);
    s1 = min(max(s1, 0), Nn - 1);
    d0 = min(max(d0, 0), Nn - 1);
    d1 = min(max(d1, 0), Nn - 1);
    if (d0 == d1) {
        int pos = atomicAdd(&g_cursor[d0], 2);
        g_edges[pos]     = s0;
        g_edges[pos + 1] = s1;
    } else {
        g_edges[atomicAdd(&g_cursor[d0], 1)] = s0;
        g_edges[atomicAdd(&g_cursor[d1], 1)] = s1;
    }
}

// ---------------- layer 1 matmul (128->32), K-tiled; fp16 h' epilogue --------
__global__ void k_mm1(const float* __restrict__ x,
                      const float* __restrict__ W1) {
    __shared__ float Xs[64 * 32];     // one 64x32 K-tile
    __shared__ float Ws[INC * C];
    int t = threadIdx.x;
    int base = blockIdx.x * 64;
    {
        const float4* w4 = (const float4*)W1;
        float4* Ws4 = (float4*)Ws;
        for (int i = t; i < INC * C / 4; i += 256) Ws4[i] = w4[i];
    }
    int warp = t >> 5, lane = t & 31;
    float acc[8] = {0.f, 0.f, 0.f, 0.f, 0.f, 0.f, 0.f, 0.f};
    const float4* x4 = (const float4*)x;
    float4* Xs4 = (float4*)Xs;
#pragma unroll
    for (int kt = 0; kt < 4; kt++) {
        __syncthreads();
        for (int i = t; i < 64 * 8; i += 256) {
            int row = i >> 3, c4 = i & 7;
            Xs4[i] = x4[(size_t)(base + row) * 32 + kt * 8 + c4];
        }
        __syncthreads();
        const float* xw = Xs + warp * 8 * 32;
#pragma unroll
        for (int k4 = 0; k4 < 8; k4++) {
            int k = kt * 32 + k4 * 4;
            float w0 = Ws[(k + 0) * C + lane];
            float w1 = Ws[(k + 1) * C + lane];
            float w2 = Ws[(k + 2) * C + lane];
            float w3 = Ws[(k + 3) * C + lane];
#pragma unroll
            for (int n = 0; n < 8; n++) {
                float4 xv = ((const float4*)(xw + n * 32))[k4];
                acc[n] = fmaf(xv.x, w0, acc[n]);
                acc[n] = fmaf(xv.y, w1, acc[n]);
                acc[n] = fmaf(xv.z, w2, acc[n]);
                acc[n] = fmaf(xv.w, w3, acc[n]);
            }
        }
    }
#pragma unroll
    for (int n = 0; n < 8; n++) {
        int i = base + warp * 8 + n;
        g_h[i * C + lane] = __float2half(acc[n] * g_dis[i]);
    }
}

// ------------- CSR gather core (fp16 rows, full warp per edge) ---------------
__device__ __forceinline__ float gather_core(int i, int e0, int e1, int lane) {
    const __half* __restrict__ h = g_h;
    const int4* ep = (const int4*)(g_edges + e0);
    int ng = (e1 - e0) >> 2;          // padded groups (pads hit zero row)
    float acc = __half2float(h[i * C + lane]);
    int g4 = 0;
    for (; g4 + 4 <= ng; g4 += 4) {
        int4 pa = ep[g4 + 0];
        int4 pb = ep[g4 + 1];
        int4 pc = ep[g4 + 2];
        int4 pd = ep[g4 + 3];
        float v0 = __half2float(h[pa.x * C + lane]);
        float v1 = __half2float(h[pa.y * C + lane]);
        float v2 = __half2float(h[pa.z * C + lane]);
        float v3 = __half2float(h[pa.w * C + lane]);
        float v4 = __half2float(h[pb.x * C + lane]);
        float v5 = __half2float(h[pb.y * C + lane]);
        float v6 = __half2float(h[pb.z * C + lane]);
        float v7 = __half2float(h[pb.w * C + lane]);
        float v8 = __half2float(h[pc.x * C + lane]);
        float v9 = __half2float(h[pc.y * C + lane]);
        float va = __half2float(h[pc.z * C + lane]);
        float vb = __half2float(h[pc.w * C + lane]);
        float vc = __half2float(h[pd.x * C + lane]);
        float vd = __half2float(h[pd.y * C + lane]);
        float ve = __half2float(h[pd.z * C + lane]);
        float vf = __half2float(h[pd.w * C + lane]);
        acc += (((v0 + v1) + (v2 + v3)) + ((v4 + v5) + (v6 + v7)))
             + (((v8 + v9) + (va + vb)) + ((vc + vd) + (ve + vf)));
    }
    for (; g4 < ng; g4++) {
        int4 p = ep[g4];
        float v0 = __half2float(h[p.x * C + lane]);
        float v1 = __half2float(h[p.y * C + lane]);
        float v2 = __half2float(h[p.z * C + lane]);
        float v3 = __half2float(h[p.w * C + lane]);
        acc += (v0 + v1) + (v2 + v3);
    }
    return acc;
}

// ----- gather (4 sequential nodes/warp) + agg + fused BN stats (layers 1,2) --
// grid = Nn/32 blocks of 8 warps (4 consecutive nodes per warp)
__global__ void __launch_bounds__(256) k_gather_stats(int sel, const float* __restrict__ b, int pass) {
    float* __restrict__ agg = (float*)selbuf(sel);
    __shared__ float shS[32], shQ[32];
    int t = threadIdx.x;
    int lane = t & 31;
    float bias = b[lane];
    if (t < 32) { shS[t] = 0.f; shQ[t] = 0.f; }
    __syncthreads();
    int i0 = (blockIdx.x * 8 + (t >> 5)) * 4;
    int4 rp = *(const int4*)(g_rowptr + i0);       // 16B-aligned (i0 % 4 == 0)
    int  rp4 = g_rowptr[i0 + 4];
    float out0 = fmaf(gather_core(i0,     rp.x, rp.y, lane), g_dis[i0],     bias);
    float out1 = fmaf(gather_core(i0 + 1, rp.y, rp.z, lane), g_dis[i0 + 1], bias);
    float out2 = fmaf(gather_core(i0 + 2, rp.z, rp.w, lane), g_dis[i0 + 2], bias);
    float out3 = fmaf(gather_core(i0 + 3, rp.w, rp4,  lane), g_dis[i0 + 3], bias);
    agg[i0 * C + lane]       = out0;
    agg[(i0 + 1) * C + lane] = out1;
    agg[(i0 + 2) * C + lane] = out2;
    agg[(i0 + 3) * C + lane] = out3;
    atomicAdd(&shS[lane], (out0 + out1) + (out2 + out3));
    atomicAdd(&shQ[lane], (out0 * out0 + out1 * out1) + (out2 * out2 + out3 * out3));
    __syncthreads();
    if (t < 32) {
        int off = pass * (SBLK * 64) + (blockIdx.x & (SBLK - 1)) * 64;
        atomicAdd(&g_part[off + t],      shS[t]);
        atomicAdd(&g_part[off + 32 + t], shQ[t]);
    }
}

// ----- gather (4 nodes/warp) + fused pooling (layer 3) -----------------------
__global__ void __launch_bounds__(256) k_gather_pool(const float* __restrict__ b,
                                                     const void* __restrict__ batchv) {
    int t = threadIdx.x;
    int lane = t & 31;
    float bias = b[lane];
    int i0 = (blockIdx.x * 8 + (t >> 5)) * 4;
    int4 rp = *(const int4*)(g_rowptr + i0);
    int  rp4 = g_rowptr[i0 + 4];
    float out0 = fmaf(gather_core(i0,     rp.x, rp.y, lane), g_dis[i0],     bias);
    float out1 = fmaf(gather_core(i0 + 1, rp.y, rp.z, lane), g_dis[i0 + 1], bias);
    float out2 = fmaf(gather_core(i0 + 2, rp.z, rp.w, lane), g_dis[i0 + 2], bias);
    float out3 = fmaf(gather_core(i0 + 3, rp.w, rp4,  lane), g_dis[i0 + 3], bias);
    int b0, b1, b2, b3;
    if (g_is64) {
        const long long* bt = (const long long*)batchv;
        b0 = (int)bt[i0]; b1 = (int)bt[i0 + 1]; b2 = (int)bt[i0 + 2]; b3 = (int)bt[i0 + 3];
    } else {
        const int* bt = (const int*)batchv;
        b0 = bt[i0]; b1 = bt[i0 + 1]; b2 = bt[i0 + 2]; b3 = bt[i0 + 3];
    }
    b0 = min(max(b0, 0), Gg - 1);
    b1 = min(max(b1, 0), Gg - 1);
    b2 = min(max(b2, 0), Gg - 1);
    b3 = min(max(b3, 0), Gg - 1);
    // merge runs of equal graph ids (batch is sorted)
    float accv = out0;
    int cur = b0;
    if (b1 == cur) accv += out1; else { atomicAdd(&g_pool[cur * C + lane], accv); cur = b1; accv = out1; }
    if (b2 == cur) accv += out2; else { atomicAdd(&g_pool[cur * C + lane], accv); cur = b2; accv = out2; }
    if (b3 == cur) accv += out3; else { atomicAdd(&g_pool[cur * C + lane], accv); cur = b3; accv = out3; }
    atomicAdd(&g_pool[cur * C + lane], accv);
}

// ------------------------- BN stats (MLP passes only) ------------------------
__global__ void k_stats(int sel, int n, int pass) {
    const float* __restrict__ a = selbuf(sel);
    int lane = threadIdx.x & 31, warp = threadIdx.x >> 5;
    int nwt = gridDim.x * 8;
    float s = 0.f, q = 0.f;
    for (int i = blockIdx.x * 8 + warp; i < n; i += nwt) {
        float v = a[i * C + lane];
        s += v;
        q += v * v;
    }
    __shared__ float ss[8][32], sq[8][32];
    ss[warp][lane] = s;
    sq[warp][lane] = q;
    __syncthreads();
    if (warp == 0) {
        float S = 0.f, Q = 0.f;
#pragma unroll
        for (int w = 0; w < 8; w++) { S += ss[w][lane]; Q += sq[w][lane]; }
        g_part[pass * (SBLK * 64) + blockIdx.x * 64 + lane]      = S;
        g_part[pass * (SBLK * 64) + blockIdx.x * 64 + 32 + lane] = Q;
    }
}

// finalize: sum partials (fp64 registers only), emit scale/shift per channel
__global__ void k_finalize(int pass, int nb, float n,
                           const float* __restrict__ gamma,
                           const float* __restrict__ beta) {
    int c = threadIdx.x;   // 32 threads
    double S = 0.0, Q = 0.0;
    const float* p = &g_part[pass * (SBLK * 64)];
    for (int b = 0; b < nb; b++) {
        S += (double)p[b * 64 + c];
        Q += (double)p[b * 64 + 32 + c];
    }
    double m   = S / (double)n;
    double var = Q / (double)n - m * m;
    if (var < 0.0) var = 0.0;
    float r  = rsqrtf((float)var + EPSF);
    float sc = r * gamma[c];
    g_bnco[pass * 64 + c]      = sc;
    g_bnco[pass * 64 + 32 + c] = beta[c] - (float)m * sc;
}

// -------- fused BN-apply + ReLU + matmul (32->32); fp16 h' epilogue ----------
__global__ void k_mm_small(int selIn, int pass,
                           const float* __restrict__ W) {
    const float* __restrict__ ain = selbuf(selIn);
    __shared__ float Xs[64 * C];
    __shared__ float Ws[C * C];
    __shared__ float bn[64];
    int t = threadIdx.x;
    int base = blockIdx.x * 64;
    if (t < 64) bn[t] = g_bnco[pass * 64 + t];
    {
        const float4* w4 = (const float4*)W;
        float4* Ws4 = (float4*)Ws;
        for (int i = t; i < C * C / 4; i += 256) Ws4[i] = w4[i];
    }
    __syncthreads();
    for (int i = t; i < 64 * C; i += 256) {
        int ch = i & 31;
        float a = ain[base * C + i];
        Xs[i] = fmaxf(a * bn[ch] + bn[32 + ch], 0.f);
    }
    __syncthreads();
    int warp = t >> 5, lane = t & 31;
    float acc[8] = {0.f, 0.f, 0.f, 0.f, 0.f, 0.f, 0.f, 0.f};
    const float* xw = Xs + warp * 8 * C;
#pragma unroll
    for (int k4 = 0; k4 < C / 4; k4++) {
        float w0 = Ws[(k4 * 4 + 0) * C + lane];
        float w1 = Ws[(k4 * 4 + 1) * C + lane];
        float w2 = Ws[(k4 * 4 + 2) * C + lane];
        float w3 = Ws[(k4 * 4 + 3) * C + lane];
#pragma unroll
        for (int n = 0; n < 8; n++) {
            float4 xv = ((const float4*)(xw + n * C))[k4];
            acc[n] = fmaf(xv.x, w0, acc[n]);
            acc[n] = fmaf(xv.y, w1, acc[n]);
            acc[n] = fmaf(xv.z, w2, acc[n]);
            acc[n] = fmaf(xv.w, w3, acc[n]);
        }
    }
#pragma unroll
    for (int n = 0; n < 8; n++) {
        int i = base + warp * 8 + n;
        g_h[i * C + lane] = __float2half(acc[n] * g_dis[i]);
    }
}

// ------------------------- MLP head -------------------------
__global__ void k_mlp_mm1(const float* __restrict__ M1, const float* __restrict__ mb1) {
    __shared__ float Ws[C * C];
    for (int t = threadIdx.x; t < C * C; t += blockDim.x) Ws[t] = M1[t];
    __syncthreads();
    int warp = threadIdx.x >> 5, lane = threadIdx.x & 31;
    int g = blockIdx.x * 8 + warp;
    if (g >= Gg) return;
    float z = g_pool[g * C + lane];
    float acc = mb1[lane];
#pragma unroll
    for (int k = 0; k < C; k++) {
        float zk = __shfl_sync(0xffffffffu, z, k);
        acc = fmaf(zk, Ws[k * C + lane], acc);
    }
    g_mlpA[g * C + lane] = acc;
}

__global__ void k_mlp_mm2(const float* __restrict__ M2, const float* __restrict__ mb2) {
    __shared__ float Ws[C * C];
    for (int t = threadIdx.x; t < C * C; t += blockDim.x) Ws[t] = M2[t];
    __syncthreads();
    int warp = threadIdx.x >> 5, lane = threadIdx.x & 31;
    int g = blockIdx.x * 8 + warp;
    if (g >= Gg) return;
    float sc = g_bnco[2 * 64 + lane];
    float sh = g_bnco[2 * 64 + 32 + lane];
    float a = g_mlpA[g * C + lane];
    float z = fmaxf(a * sc + sh, 0.f);
    float acc = mb2[lane];
#pragma unroll
    for (int k = 0; k < C; k++) {
        float zk = __shfl_sync(0xffffffffu, z, k);
        acc = fmaf(zk, Ws[k * C + lane], acc);
    }
    g_mlpB[g * C + lane] = acc;
}

__global__ void k_mlp_out(const float* __restrict__ M3, const float* __restrict__ mb3,
                          float* __restrict__ out) {
    int lane = threadIdx.x & 31;
    int g = blockIdx.x * (blockDim.x >> 5) + (threadIdx.x >> 5);
    if (g >= Gg) return;
    float sc = g_bnco[3 * 64 + lane];
    float sh = g_bnco[3 * 64 + 32 + lane];
    float v  = g_mlpB[g * C + lane];
    float z  = fmaxf(v * sc + sh, 0.f);
    float t  = z * M3[lane];
#pragma unroll
    for (int o = 16; o; o >>= 1) t += __shfl_down_sync(0xffffffffu, t, o);
    if (lane == 0) out[g] = t + mb3[0];
}

// ------------------------- launch -------------------------
extern "C" void kernel_launch(void* const* d_in, const int* in_sizes, int n_in,
                              void* d_out, int out_size) {
    (void)in_sizes; (void)n_in; (void)out_size;
    const float* x     = (const float*)d_in[0];
    const void*  ei    = d_in[1];
    const void*  batch = d_in[2];
    const float* W1  = (const float*)d_in[3];
    const float* b1  = (const float*)d_in[4];
    const float* gm1 = (const float*)d_in[5];
    const float* be1 = (const float*)d_in[6];
    const float* W2  = (const float*)d_in[7];
    const float* b2  = (const float*)d_in[8];
    const float* gm2 = (const float*)d_in[9];
    const float* be2 = (const float*)d_in[10];
    const float* W3  = (const float*)d_in[11];
    const float* b3  = (const float*)d_in[12];
    const float* M1  = (const float*)d_in[13];
    const float* mb1 = (const float*)d_in[14];
    const float* mg1 = (const float*)d_in[15];
    const float* mbe1= (const float*)d_in[16];
    const float* M2  = (const float*)d_in[17];
    const float* mb2 = (const float*)d_in[18];
    const float* mg2 = (const float*)d_in[19];
    const float* mbe2= (const float*)d_in[20];
    const float* M3  = (const float*)d_in[21];
    const float* mb3 = (const float*)d_in[22];
    float* out = (float*)d_out;

    const int TB = 256;
    k_init<<<800, TB>>>((const unsigned int*)ei);
    k_count<<<(Ee / 2 + TB - 1) / TB, TB>>>(ei);
    k_scan1<<<NSB, SCB>>>();
    k_scan2<<<1, 1024>>>();
    k_scan3<<<NSB, SCB>>>();                               // writes g_dis + pads
    k_mm1<<<Nn / 64, TB>>>(x, W1);                         // reads g_dis
    k_sort<<<(Ee / 2 + TB - 1) / TB, TB>>>(ei);

    // layer 1: conv(x) -> aggA (+fused stats pass 0)
    k_gather_stats<<<Nn / 32, TB>>>(0, b1, 0);
    k_finalize<<<1, 32>>>(0, SBLK, (float)Nn, gm1, be1);

    // layer 2: relu(bn(aggA)) @ W2 -> aggB (+fused stats pass 1)
    k_mm_small<<<Nn / 64, TB>>>(0, 0, W2);
    k_gather_stats<<<Nn / 32, TB>>>(1, b2, 1);
    k_finalize<<<1, 32>>>(1, SBLK, (float)Nn, gm2, be2);

    // layer 3: relu(bn(aggB)) @ W3 -> pooled directly
    k_mm_small<<<Nn / 64, TB>>>(1, 1, W3);
    k_gather_pool<<<Nn / 32, TB>>>(b3, batch);

    // MLP head
    k_mlp_mm1<<<Gg / 8, TB>>>(M1, mb1);
    k_stats<<<SBLK_G, TB>>>(2, Gg, 2);
    k_finalize<<<1, 32>>>(2, SBLK_G, (float)Gg, mg1, mbe1);
    k_mlp_mm2<<<Gg / 8, TB>>>(M2, mb2);
    k_stats<<<SBLK_G, TB>>>(3, Gg, 3);
    k_finalize<<<1, 32>>>(3, SBLK_G, (float)Gg, mg2, mbe2);
    k_mlp_out<<<Gg / 8, TB>>>(M3, mb3, out);
}

// round 16
// speedup vs baseline: 1.0194x; 1.0194x over previous
#include <cuda_runtime.h>
#include <cuda_fp16.h>
#include <mma.h>

#define Nn 200000
#define Ee 6400000
#define EPAD (Ee + 4 * Nn)
#define Gg 1024
#define C  32
#define INC 128
#define EPSF 1e-5f
#define SBLK 128          // partial slots for node-level BN stats
#define SBLK_G 8          // blocks for graph-level BN stats
#define SCB 256           // nodes per scan block
#define NSB ((Nn + SCB - 1) / SCB)   // 782 scan blocks

using namespace nvcuda;

// ------------------------- scratch (device globals) -------------------------
__device__ int    g_edges[EPAD];      // CSR-sorted src per dst, 4-padded (pad = Nn)
__device__ int    g_degi[Nn];
__device__ int    g_rowptr[Nn + 1];   // 4-aligned segment starts
__device__ int    g_cursor[Nn];
__device__ int    g_bsum[NSB];
__device__ int    g_boff[NSB];
__device__ float  g_dis[Nn];
__device__ __half g_h[(Nn + 1) * C];  // h' = h*dis (fp16); row Nn stays zero
__device__ float  g_aggA[Nn * C];
__device__ float  g_aggB[Nn * C];
__device__ float  g_mlpA[Gg * C];
__device__ float  g_mlpB[Gg * C];
__device__ float  g_pool[Gg * C];
__device__ float  g_part[4 * SBLK * 64];  // per-pass {sum[32], sumsq[32]} slots
__device__ float  g_bnco[4 * 64];         // per-pass {scale[32], shift[32]}
__device__ int    g_is64;                 // 1 if index inputs are int64, 0 if int32

__device__ __forceinline__ const float* selbuf(int s) {
    if (s == 0) return g_aggA;
    if (s == 1) return g_aggB;
    if (s == 2) return g_mlpA;
    return g_mlpB;
}

// ------------------------- init: dtype detect + zeroing ----------------------
__global__ void k_init(const unsigned int* __restrict__ w) {
    if (blockIdx.x == 0 && threadIdx.x < 32) {
        unsigned int acc = 0;
        for (int i = threadIdx.x; i < 2048; i += 32)
            if (i & 1) acc |= w[i];
#pragma unroll
        for (int o = 16; o; o >>= 1) acc |= __shfl_down_sync(0xffffffffu, acc, o);
        if (threadIdx.x == 0) g_is64 = (acc == 0u) ? 1 : 0;
    }
    int idx = blockIdx.x * blockDim.x + threadIdx.x;
    int stride = gridDim.x * blockDim.x;
    for (int i = idx; i < Nn; i += stride)            g_degi[i] = 0;
    for (int i = idx; i < Gg * C; i += stride)        g_pool[i] = 0.f;
    for (int i = idx; i < 2 * SBLK * 64; i += stride) g_part[i] = 0.f;
    for (int i = idx; i < C; i += stride)             g_h[Nn * C + i] = __float2half(0.f);
}

// count in-degree (dst half only, 2 edges/thread, vector loads)
__global__ void k_count(const void* __restrict__ eiv) {
    int p = blockIdx.x * blockDim.x + threadIdx.x;   // pair index
    int e = p * 2;
    if (e >= Ee) return;
    int d0, d1;
    if (g_is64) {
        longlong2 v = ((const longlong2*)((const long long*)eiv + Ee))[p];
        d0 = (int)v.x; d1 = (int)v.y;
    } else {
        int2 v = ((const int2*)((const int*)eiv + Ee))[p];
        d0 = v.x; d1 = v.y;
    }
    d0 = min(max(d0, 0), Nn - 1);
    d1 = min(max(d1, 0), Nn - 1);
    if (d0 == d1) {
        atomicAdd(&g_degi[d0], 2);
    } else {
        atomicAdd(&g_degi[d0], 1);
        atomicAdd(&g_degi[d1], 1);
    }
}

// ------------------------- multi-block exclusive scan over PADDED degrees ----
__global__ void k_scan1() {
    __shared__ int sh[SCB / 32];
    int t = threadIdx.x;
    int i = blockIdx.x * SCB + t;
    int v = (i < Nn) ? ((g_degi[i] + 3) & ~3) : 0;
#pragma unroll
    for (int o = 16; o; o >>= 1) v += __shfl_down_sync(0xffffffffu, v, o);
    if ((t & 31) == 0) sh[t >> 5] = v;
    __syncthreads();
    if (t < SCB / 32) {
        int s = sh[t];
#pragma unroll
        for (int o = SCB / 64; o; o >>= 1) s += __shfl_down_sync(0xffffffffu, s, o);
        if (t == 0) g_bsum[blockIdx.x] = s;
    }
}

__global__ void k_scan2() {
    __shared__ int bs[1024];
    int t = threadIdx.x;
    int v = (t < NSB) ? g_bsum[t] : 0;
    bs[t] = v;
    __syncthreads();
    for (int o = 1; o < 1024; o <<= 1) {
        int u = (t >= o) ? bs[t - o] : 0;
        __syncthreads();
        bs[t] += u;
        __syncthreads();
    }
    if (t < NSB) g_boff[t] = bs[t] - v;          // exclusive
    if (t == NSB - 1) g_rowptr[Nn] = bs[t];      // total padded count
}

// scan3: rowptr/cursor/dis AND pad-slot fill (sort won't touch pad slots)
__global__ void k_scan3() {
    __shared__ int sh[SCB];
    int t = threadIdx.x;
    int i = blockIdx.x * SCB + t;
    int deg = (i < Nn) ? g_degi[i] : 0;
    int pdeg = (deg + 3) & ~3;
    sh[t] = pdeg;
    __syncthreads();
    int incl = pdeg;
    for (int o = 1; o < SCB; o <<= 1) {
        int u = (t >= o) ? sh[t - o] : 0;
        __syncthreads();
        incl += u;
        sh[t] = incl;
        __syncthreads();
    }
    if (i < Nn) {
        int off = g_boff[blockIdx.x] + incl - pdeg;
        g_rowptr[i] = off;
        g_cursor[i] = off;
        g_dis[i] = rsqrtf((float)deg + 1.0f);
        for (int j = off + deg; j < off + pdeg; j++) g_edges[j] = Nn;  // pads
    }
}

// ------------- counting-sort edges into padded CSR (2 edges/thread) ----------
__global__ void k_sort(const void* __restrict__ eiv) {
    int p = blockIdx.x * blockDim.x + threadIdx.x;
    int e = p * 2;
    if (e >= Ee) return;
    int s0, s1, d0, d1;
    if (g_is64) {
        const long long* ei = (const long long*)eiv;
        longlong2 sv = ((const longlong2*)ei)[p];
        longlong2 dv = ((const longlong2*)(ei + Ee))[p];
        s0 = (int)sv.x; s1 = (int)sv.y;
        d0 = (int)dv.x; d1 = (int)dv.y;
    } else {
        const int* ei = (const int*)eiv;
        int2 sv = ((const int2*)ei)[p];
        int2 dv = ((const int2*)(ei + Ee))[p];
        s0 = sv.x; s1 = sv.y;
        d0 = dv.x; d1 = dv.y;
    }
    s0 = min(max(s0, 0), Nn - 1);
    s1 = min(max(s1, 0), Nn - 1);
    d0 = min(max(d0, 0), Nn - 1);
    d1 = min(max(d1, 0), Nn - 1);
    if (d0 == d1) {
        int pos = atomicAdd(&g_cursor[d0], 2);
        g_edges[pos]     = s0;
        g_edges[pos + 1] = s1;
    } else {
        g_edges[atomicAdd(&g_cursor[d0], 1)] = s0;
        g_edges[atomicAdd(&g_cursor[d1], 1)] = s1;
    }
}

// ---------------- layer 1 matmul (128->32) via wmma tensor cores -------------
// 128 threads (4 warps), 64 rows per block; grid = Nn/64 = 3125 exactly.
// fp16 inputs, fp32 accumulate; epilogue scales by dis, writes fp16 h'.
__global__ void __launch_bounds__(128) k_mm1(const float* __restrict__ x,
                                             const float* __restrict__ W1) {
    __shared__ __half Xs[64 * INC];      // 16 KB
    __shared__ __half Ws[INC * C];       // 8 KB
    __shared__ float  St[4][16 * 32];    // 8 KB staging (one 16x32 tile per warp)
    int t = threadIdx.x;
    int base = blockIdx.x * 64;
    // W1 -> fp16 smem (4096 elements)
    for (int i = t; i < INC * C / 2; i += 128) {
        float2 v = ((const float2*)W1)[i];
        ((__half2*)Ws)[i] = __floats2half2_rn(v.x, v.y);
    }
    // x tile -> fp16 smem (64 rows x 128 cols), coalesced float2 loads
    for (int i = t; i < 64 * INC / 2; i += 128) {
        float2 v = ((const float2*)x)[(size_t)base * (INC / 2) + i];
        ((__half2*)Xs)[i] = __floats2half2_rn(v.x, v.y);
    }
    __syncthreads();
    int warp = t >> 5, lane = t & 31;
    wmma::fragment<wmma::accumulator, 16, 16, 16, float> c0, c1;
    wmma::fill_fragment(c0, 0.f);
    wmma::fill_fragment(c1, 0.f);
#pragma unroll
    for (int k = 0; k < INC / 16; k++) {
        wmma::fragment<wmma::matrix_a, 16, 16, 16, __half, wmma::row_major> a;
        wmma::load_matrix_sync(a, Xs + warp * 16 * INC + k * 16, INC);
        wmma::fragment<wmma::matrix_b, 16, 16, 16, __half, wmma::row_major> b0, b1;
        wmma::load_matrix_sync(b0, Ws + k * 16 * C, C);
        wmma::load_matrix_sync(b1, Ws + k * 16 * C + 16, C);
        wmma::mma_sync(c0, a, b0, c0);
        wmma::mma_sync(c1, a, b1, c1);
    }
    wmma::store_matrix_sync(&St[warp][0],  c0, 32, wmma::mem_row_major);
    wmma::store_matrix_sync(&St[warp][16], c1, 32, wmma::mem_row_major);
    __syncwarp();
#pragma unroll
    for (int r = 0; r < 16; r++) {
        int i = base + warp * 16 + r;
        g_h[i * C + lane] = __float2half(St[warp][r * 32 + lane] * g_dis[i]);
    }
}

// ------------- CSR gather core (fp16 rows, full warp per edge) ---------------
__device__ __forceinline__ float gather_core(int i, int e0, int e1, int lane) {
    const __half* __restrict__ h = g_h;
    const int4* ep = (const int4*)(g_edges + e0);
    int ng = (e1 - e0) >> 2;          // padded groups (pads hit zero row)
    float acc = __half2float(h[i * C + lane]);
    int g4 = 0;
    for (; g4 + 4 <= ng; g4 += 4) {
        int4 pa = ep[g4 + 0];
        int4 pb = ep[g4 + 1];
        int4 pc = ep[g4 + 2];
        int4 pd = ep[g4 + 3];
        float v0 = __half2float(h[pa.x * C + lane]);
        float v1 = __half2float(h[pa.y * C + lane]);
        float v2 = __half2float(h[pa.z * C + lane]);
        float v3 = __half2float(h[pa.w * C + lane]);
        float v4 = __half2float(h[pb.x * C + lane]);
        float v5 = __half2float(h[pb.y * C + lane]);
        float v6 = __half2float(h[pb.z * C + lane]);
        float v7 = __half2float(h[pb.w * C + lane]);
        float v8 = __half2float(h[pc.x * C + lane]);
        float v9 = __half2float(h[pc.y * C + lane]);
        float va = __half2float(h[pc.z * C + lane]);
        float vb = __half2float(h[pc.w * C + lane]);
        float vc = __half2float(h[pd.x * C + lane]);
        float vd = __half2float(h[pd.y * C + lane]);
        float ve = __half2float(h[pd.z * C + lane]);
        float vf = __half2float(h[pd.w * C + lane]);
        acc += (((v0 + v1) + (v2 + v3)) + ((v4 + v5) + (v6 + v7)))
             + (((v8 + v9) + (va + vb)) + ((vc + vd) + (ve + vf)));
    }
    for (; g4 < ng; g4++) {
        int4 p = ep[g4];
        float v0 = __half2float(h[p.x * C + lane]);
        float v1 = __half2float(h[p.y * C + lane]);
        float v2 = __half2float(h[p.z * C + lane]);
        float v3 = __half2float(h[p.w * C + lane]);
        acc += (v0 + v1) + (v2 + v3);
    }
    return acc;
}

// ----- gather (2 sequential nodes/warp) + agg + fused BN stats (layers 1,2) --
// grid = Nn/16 blocks of 8 warps (2 consecutive nodes per warp)
__global__ void __launch_bounds__(256) k_gather_stats(int sel, const float* __restrict__ b, int pass) {
    float* __restrict__ agg = (float*)selbuf(sel);
    __shared__ float shS[32], shQ[32];
    int t = threadIdx.x;
    int lane = t & 31;
    float bias = b[lane];
    if (t < 32) { shS[t] = 0.f; shQ[t] = 0.f; }
    __syncthreads();
    int i0 = (blockIdx.x * 8 + (t >> 5)) * 2;
    int2 rp01 = *(const int2*)(g_rowptr + i0);     // 8B-aligned (i0 even)
    int  rp2  = g_rowptr[i0 + 2];
    float out0 = fmaf(gather_core(i0,     rp01.x, rp01.y, lane), g_dis[i0],     bias);
    float out1 = fmaf(gather_core(i0 + 1, rp01.y, rp2,    lane), g_dis[i0 + 1], bias);
    agg[i0 * C + lane]       = out0;
    agg[(i0 + 1) * C + lane] = out1;
    atomicAdd(&shS[lane], out0 + out1);
    atomicAdd(&shQ[lane], out0 * out0 + out1 * out1);
    __syncthreads();
    if (t < 32) {
        int off = pass * (SBLK * 64) + (blockIdx.x & (SBLK - 1)) * 64;
        atomicAdd(&g_part[off + t],      shS[t]);
        atomicAdd(&g_part[off + 32 + t], shQ[t]);
    }
}

// ----- gather (2 nodes/warp) + fused pooling (layer 3) -----------------------
__global__ void __launch_bounds__(256) k_gather_pool(const float* __restrict__ b,
                                                     const void* __restrict__ batchv) {
    int t = threadIdx.x;
    int lane = t & 31;
    float bias = b[lane];
    int i0 = (blockIdx.x * 8 + (t >> 5)) * 2;
    int2 rp01 = *(const int2*)(g_rowptr + i0);
    int  rp2  = g_rowptr[i0 + 2];
    float out0 = fmaf(gather_core(i0,     rp01.x, rp01.y, lane), g_dis[i0],     bias);
    float out1 = fmaf(gather_core(i0 + 1, rp01.y, rp2,    lane), g_dis[i0 + 1], bias);
    int b0, b1;
    if (g_is64) {
        b0 = (int)((const long long*)batchv)[i0];
        b1 = (int)((const long long*)batchv)[i0 + 1];
    } else {
        b0 = ((const int*)batchv)[i0];
        b1 = ((const int*)batchv)[i0 + 1];
    }
    b0 = min(max(b0, 0), Gg - 1);
    b1 = min(max(b1, 0), Gg - 1);
    if (b0 == b1) {
        atomicAdd(&g_pool[b0 * C + lane], out0 + out1);
    } else {
        atomicAdd(&g_pool[b0 * C + lane], out0);
        atomicAdd(&g_pool[b1 * C + lane], out1);
    }
}

// ------------------------- BN stats (MLP passes only) ------------------------
__global__ void k_stats(int sel, int n, int pass) {
    const float* __restrict__ a = selbuf(sel);
    int lane = threadIdx.x & 31, warp = threadIdx.x >> 5;
    int nwt = gridDim.x * 8;
    float s = 0.f, q = 0.f;
    for (int i = blockIdx.x * 8 + warp; i < n; i += nwt) {
        float v = a[i * C + lane];
        s += v;
        q += v * v;
    }
    __shared__ float ss[8][32], sq[8][32];
    ss[warp][lane] = s;
    sq[warp][lane] = q;
    __syncthreads();
    if (warp == 0) {
        float S = 0.f, Q = 0.f;
#pragma unroll
        for (int w = 0; w < 8; w++) { S += ss[w][lane]; Q += sq[w][lane]; }
        g_part[pass * (SBLK * 64) + blockIdx.x * 64 + lane]      = S;
        g_part[pass * (SBLK * 64) + blockIdx.x * 64 + 32 + lane] = Q;
    }
}

// finalize: sum partials (fp64 registers only), emit scale/shift per channel
__global__ void k_finalize(int pass, int nb, float n,
                           const float* __restrict__ gamma,
                           const float* __restrict__ beta) {
    int c = threadIdx.x;   // 32 threads
    double S = 0.0, Q = 0.0;
    const float* p = &g_part[pass * (SBLK * 64)];
    for (int b = 0; b < nb; b++) {
        S += (double)p[b * 64 + c];
        Q += (double)p[b * 64 + 32 + c];
    }
    double m   = S / (double)n;
    double var = Q / (double)n - m * m;
    if (var < 0.0) var = 0.0;
    float r  = rsqrtf((float)var + EPSF);
    float sc = r * gamma[c];
    g_bnco[pass * 64 + c]      = sc;
    g_bnco[pass * 64 + 32 + c] = beta[c] - (float)m * sc;
}

// -------- fused BN-apply + ReLU + matmul (32->32); fp16 h' epilogue ----------
__global__ void k_mm_small(int selIn, int pass,
                           const float* __restrict__ W) {
    const float* __restrict__ ain = selbuf(selIn);
    __shared__ float Xs[64 * C];
    __shared__ float Ws[C * C];
    __shared__ float bn[64];
    int t = threadIdx.x;
    int base = blockIdx.x * 64;
    if (t < 64) bn[t] = g_bnco[pass * 64 + t];
    {
        const float4* w4 = (const float4*)W;
        float4* Ws4 = (float4*)Ws;
        for (int i = t; i < C * C / 4; i += 256) Ws4[i] = w4[i];
    }
    __syncthreads();
    for (int i = t; i < 64 * C; i += 256) {
        int ch = i & 31;
        float a = ain[base * C + i];
        Xs[i] = fmaxf(a * bn[ch] + bn[32 + ch], 0.f);
    }
    __syncthreads();
    int warp = t >> 5, lane = t & 31;
    float acc[8] = {0.f, 0.f, 0.f, 0.f, 0.f, 0.f, 0.f, 0.f};
    const float* xw = Xs + warp * 8 * C;
#pragma unroll
    for (int k4 = 0; k4 < C / 4; k4++) {
        float w0 = Ws[(k4 * 4 + 0) * C + lane];
        float w1 = Ws[(k4 * 4 + 1) * C + lane];
        float w2 = Ws[(k4 * 4 + 2) * C + lane];
        float w3 = Ws[(k4 * 4 + 3) * C + lane];
#pragma unroll
        for (int n = 0; n < 8; n++) {
            float4 xv = ((const float4*)(xw + n * C))[k4];
            acc[n] = fmaf(xv.x, w0, acc[n]);
            acc[n] = fmaf(xv.y, w1, acc[n]);
            acc[n] = fmaf(xv.z, w2, acc[n]);
            acc[n] = fmaf(xv.w, w3, acc[n]);
        }
    }
#pragma unroll
    for (int n = 0; n < 8; n++) {
        int i = base + warp * 8 + n;
        g_h[i * C + lane] = __float2half(acc[n] * g_dis[i]);
    }
}

// ------------------------- MLP head -------------------------
__global__ void k_mlp_mm1(const float* __restrict__ M1, const float* __restrict__ mb1) {
    __shared__ float Ws[C * C];
    for (int t = threadIdx.x; t < C * C; t += blockDim.x) Ws[t] = M1[t];
    __syncthreads();
    int warp = threadIdx.x >> 5, lane = threadIdx.x & 31;
    int g = blockIdx.x * 8 + warp;
    if (g >= Gg) return;
    float z = g_pool[g * C + lane];
    float acc = mb1[lane];
#pragma unroll
    for (int k = 0; k < C; k++) {
        float zk = __shfl_sync(0xffffffffu, z, k);
        acc = fmaf(zk, Ws[k * C + lane], acc);
    }
    g_mlpA[g * C + lane] = acc;
}

__global__ void k_mlp_mm2(const float* __restrict__ M2, const float* __restrict__ mb2) {
    __shared__ float Ws[C * C];
    for (int t = threadIdx.x; t < C * C; t += blockDim.x) Ws[t] = M2[t];
    __syncthreads();
    int warp = threadIdx.x >> 5, lane = threadIdx.x & 31;
    int g = blockIdx.x * 8 + warp;
    if (g >= Gg) return;
    float sc = g_bnco[2 * 64 + lane];
    float sh = g_bnco[2 * 64 + 32 + lane];
    float a = g_mlpA[g * C + lane];
    float z = fmaxf(a * sc + sh, 0.f);
    float acc = mb2[lane];
#pragma unroll
    for (int k = 0; k < C; k++) {
        float zk = __shfl_sync(0xffffffffu, z, k);
        acc = fmaf(zk, Ws[k * C + lane], acc);
    }
    g_mlpB[g * C + lane] = acc;
}

__global__ void k_mlp_out(const float* __restrict__ M3, const float* __restrict__ mb3,
                          float* __restrict__ out) {
    int lane = threadIdx.x & 31;
    int g = blockIdx.x * (blockDim.x >> 5) + (threadIdx.x >> 5);
    if (g >= Gg) return;
    float sc = g_bnco[3 * 64 + lane];
    float sh = g_bnco[3 * 64 + 32 + lane];
    float v  = g_mlpB[g * C + lane];
    float z  = fmaxf(v * sc + sh, 0.f);
    float t  = z * M3[lane];
#pragma unroll
    for (int o = 16; o; o >>= 1) t += __shfl_down_sync(0xffffffffu, t, o);
    if (lane == 0) out[g] = t + mb3[0];
}

// ------------------------- launch -------------------------
extern "C" void kernel_launch(void* const* d_in, const int* in_sizes, int n_in,
                              void* d_out, int out_size) {
    (void)in_sizes; (void)n_in; (void)out_size;
    const float* x     = (const float*)d_in[0];
    const void*  ei    = d_in[1];
    const void*  batch = d_in[2];
    const float* W1  = (const float*)d_in[3];
    const float* b1  = (const float*)d_in[4];
    const float* gm1 = (const float*)d_in[5];
    const float* be1 = (const float*)d_in[6];
    const float* W2  = (const float*)d_in[7];
    const float* b2  = (const float*)d_in[8];
    const float* gm2 = (const float*)d_in[9];
    const float* be2 = (const float*)d_in[10];
    const float* W3  = (const float*)d_in[11];
    const float* b3  = (const float*)d_in[12];
    const float* M1  = (const float*)d_in[13];
    const float* mb1 = (const float*)d_in[14];
    const float* mg1 = (const float*)d_in[15];
    const float* mbe1= (const float*)d_in[16];
    const float* M2  = (const float*)d_in[17];
    const float* mb2 = (const float*)d_in[18];
    const float* mg2 = (const float*)d_in[19];
    const float* mbe2= (const float*)d_in[20];
    const float* M3  = (const float*)d_in[21];
    const float* mb3 = (const float*)d_in[22];
    float* out = (float*)d_out;

    const int TB = 256;
    k_init<<<800, TB>>>((const unsigned int*)ei);
    k_count<<<(Ee / 2 + TB - 1) / TB, TB>>>(ei);
    k_scan1<<<NSB, SCB>>>();
    k_scan2<<<1, 1024>>>();
    k_scan3<<<NSB, SCB>>>();                               // writes g_dis + pads
    k_mm1<<<Nn / 64, 128>>>(x, W1);                        // wmma; reads g_dis
    k_sort<<<(Ee / 2 + TB - 1) / TB, TB>>>(ei);

    // layer 1: conv(x) -> aggA (+fused stats pass 0)
    k_gather_stats<<<Nn / 16, TB>>>(0, b1, 0);
    k_finalize<<<1, 32>>>(0, SBLK, (float)Nn, gm1, be1);

    // layer 2: relu(bn(aggA)) @ W2 -> aggB (+fused stats pass 1)
    k_mm_small<<<Nn / 64, TB>>>(0, 0, W2);
    k_gather_stats<<<Nn / 16, TB>>>(1, b2, 1);
    k_finalize<<<1, 32>>>(1, SBLK, (float)Nn, gm2, be2);

    // layer 3: relu(bn(aggB)) @ W3 -> pooled directly
    k_mm_small<<<Nn / 64, TB>>>(1, 1, W3);
    k_gather_pool<<<Nn / 16, TB>>>(b3, batch);

    // MLP head
    k_mlp_mm1<<<Gg / 8, TB>>>(M1, mb1);
    k_stats<<<SBLK_G, TB>>>(2, Gg, 2);
    k_finalize<<<1, 32>>>(2, SBLK_G, (float)Gg, mg1, mbe1);
    k_mlp_mm2<<<Gg / 8, TB>>>(M2, mb2);
    k_stats<<<SBLK_G, TB>>>(3, Gg, 3);
    k_finalize<<<1, 32>>>(3, SBLK_G, (float)Gg, mg2, mbe2);
    k_mlp_out<<<Gg / 8, TB>>>(M3, mb3, out);
}